// round 13
// baseline (speedup 1.0000x reference)
#include <cuda_runtime.h>
#include <cuda_fp16.h>
#include <stdint.h>
#include <math.h>

#define BATCH 32
#define CH    512
#define NTOK  1024
#define NGRP  32
#define CPG   16

typedef unsigned int u32;

// ---------------- scratch (device globals) ----------------
__device__ __half g_h [(size_t)BATCH * NTOK * CH];   // [b][t][c]
__device__ __half g_q [(size_t)BATCH * NTOK * CH];   // [b][t][c]
__device__ __half g_k [(size_t)BATCH * NTOK * CH];   // [b][t][c]
__device__ __half g_vt[(size_t)BATCH * CH * NTOK];   // [b][c][t]
__device__ __half g_s [(size_t)BATCH * NTOK * NTOK]; // scores fp16
__device__ __half g_p [(size_t)BATCH * NTOK * NTOK]; // probs fp16
__device__ __half g_o [(size_t)BATCH * NTOK * CH];   // [b][t][c]
__device__ __half g_w [4 * CH * CH];                 // wq|wk|wv | wp(x1024)

// ---------------- weight fp32 -> fp16 ----------------
__global__ void convw_kernel(const float* __restrict__ wq, const float* __restrict__ wk,
                             const float* __restrict__ wv, const float* __restrict__ wp,
                             __half* __restrict__ w) {
    int i = blockIdx.x * 256 + threadIdx.x;
    if (i < CH * CH) {
        w[i]               = __float2half(wq[i]);
        w[CH * CH + i]     = __float2half(wk[i]);
        w[2 * CH * CH + i] = __float2half(wv[i]);
        w[3 * CH * CH + i] = __float2half(wp[i] * 1024.0f);  // avoid fp16 subnormals
    }
}

// ---------------- GroupNorm: fp32 stats, fp16 token-major out ----------------
__global__ void gn_kernel(const float* __restrict__ x,
                          const float* __restrict__ gw,
                          const float* __restrict__ gb,
                          __half* __restrict__ h) {
    const int bg = blockIdx.x;
    const int b = bg / NGRP, g = bg % NGRP;
    const int n = CPG * NTOK;
    const size_t base = (size_t)bg * n;
    const int t = threadIdx.x;

    float s = 0.f, ss = 0.f;
    for (int i = t; i < n; i += 256) {
        float v = x[base + i];
        s += v; ss += v * v;
    }
    __shared__ float rs[256], rq[256];
    rs[t] = s; rq[t] = ss;
    __syncthreads();
    for (int o = 128; o > 0; o >>= 1) {
        if (t < o) { rs[t] += rs[t + o]; rq[t] += rq[t + o]; }
        __syncthreads();
    }
    const float mean = rs[0] * (1.0f / n);
    const float var  = rq[0] * (1.0f / n) - mean * mean;
    const float rstd = rsqrtf(var + 1e-5f);

    float a[CPG], c[CPG];
    #pragma unroll
    for (int i = 0; i < CPG; i++) {
        a[i] = rstd * gw[g * CPG + i];
        c[i] = gb[g * CPG + i] - mean * a[i];
    }
    for (int tok = t; tok < NTOK; tok += 256) {
        __half buf[CPG];
        #pragma unroll
        for (int i = 0; i < CPG; i++)
            buf[i] = __float2half(x[base + (size_t)i * NTOK + tok] * a[i] + c[i]);
        size_t ho = ((size_t)(b * NTOK + tok)) * CH + g * CPG;
        uint4* dst = reinterpret_cast<uint4*>(&h[ho]);
        const uint4* src = reinterpret_cast<const uint4*>(buf);
        dst[0] = src[0];
        dst[1] = src[1];
    }
}

// ---------------- epilogue store helpers ----------------
__device__ __forceinline__ void store2(float* p, float v0, float v1) {
    *reinterpret_cast<float2*>(p) = make_float2(v0, v1);
}
__device__ __forceinline__ void store2(__half* p, float v0, float v1) {
    *reinterpret_cast<__half2*>(p) = __floats2half2_rn(v0, v1);
}

// ---------------- fp16 TN GEMM: 128x256 tile, 128 thr, 64x128 warp tile -----
// fp16 accumulate. C[m][n] = alpha*sum_k A[m][k]*B[n][k] (+bias_m/(n)) (+resid)
// A: [M][K] (ld=K), B: [N][K] (ld=K), C: [M][N]. BK=32, NSTG=3 cp.async ring.
#define BM 128
#define BN 256
#define BK 32
#define LDSW 40  // BK + 8 pad
#define NSTG 3
#define NTHR 128
#define GEMM_SMEM ((BM + BN) * LDSW * NSTG * 2)   // 92160 bytes

template<typename OutT>
__global__ void __launch_bounds__(NTHR, 2)
mma_gemm(const __half* __restrict__ A, const __half* __restrict__ B, OutT* __restrict__ C,
         int K, int N, long sA, long sB, long sC,
         float alpha, const float* __restrict__ bias_m, const float* __restrict__ bias_n,
         const float* __restrict__ resid, long sR) {
    extern __shared__ __half sm[];
    __half* Asm = sm;                       // NSTG stages of BM*LDSW
    __half* Bsm = sm + NSTG * BM * LDSW;    // NSTG stages of BN*LDSW

    const int bz = blockIdx.z;
    const __half* Ab = A + (size_t)bz * sA + (size_t)(blockIdx.y * BM) * K;
    const __half* Bb = B + (size_t)bz * sB + (size_t)(blockIdx.x * BN) * K;

    const int t = threadIdx.x;
    const int lane = t & 31, w = t >> 5;              // 4 warps
    const int wm = (w >> 1) * 64, wn = (w & 1) * 128; // 2x2 grid of 64x128

    const int lr = t >> 2;          // chunk row (0..31)
    const int lc = (t & 3) * 8;     // chunk col (elems)

    // ldmatrix base offsets
    const int a_row = wm + (lane & 15);
    const int a_col = (lane >> 4) * 8;
    const int b_row = wn + (lane & 7) + ((lane >> 4) << 3);
    const int b_col = ((lane >> 3) & 1) * 8;

    u32 acc[4][16][2];                // fp16x2 accumulators, 64x128 per warp
    #pragma unroll
    for (int i = 0; i < 4; i++)
        #pragma unroll
        for (int j = 0; j < 16; j++) { acc[i][j][0] = 0u; acc[i][j][1] = 0u; }

    auto issue = [&](int j) {
        const int st = j % NSTG;
        const int k0 = j * BK;
        #pragma unroll
        for (int i = 0; i < 4; i++) {             // A: 128 rows
            int r = lr + i * 32;
            u32 da = (u32)__cvta_generic_to_shared(&Asm[st * BM * LDSW + r * LDSW + lc]);
            const __half* ga = Ab + (size_t)r * K + k0 + lc;
            asm volatile("cp.async.cg.shared.global [%0], [%1], 16;\n" :: "r"(da), "l"(ga));
        }
        #pragma unroll
        for (int i = 0; i < 8; i++) {             // B: 256 rows
            int r = lr + i * 32;
            u32 db = (u32)__cvta_generic_to_shared(&Bsm[st * BN * LDSW + r * LDSW + lc]);
            const __half* gbp = Bb + (size_t)r * K + k0 + lc;
            asm volatile("cp.async.cg.shared.global [%0], [%1], 16;\n" :: "r"(db), "l"(gbp));
        }
        asm volatile("cp.async.commit_group;\n");
    };

    const int KT = K / BK;
    issue(0);
    if (1 < KT) issue(1);

    for (int kt = 0; kt < KT; kt++) {
        asm volatile("cp.async.wait_group 1;\n");
        __syncthreads();
        const int st = kt % NSTG;
        const __half* as = Asm + st * BM * LDSW;
        const __half* bs = Bsm + st * BN * LDSW;

        #pragma unroll
        for (int ks = 0; ks < 2; ks++) {
            u32 afrag[4][4];
            #pragma unroll
            for (int mt = 0; mt < 4; mt++) {
                u32 addr = (u32)__cvta_generic_to_shared(
                    &as[(a_row + mt * 16) * LDSW + ks * 16 + a_col]);
                asm volatile("ldmatrix.sync.aligned.m8n8.x4.shared.b16 {%0,%1,%2,%3}, [%4];\n"
                    : "=r"(afrag[mt][0]), "=r"(afrag[mt][1]),
                      "=r"(afrag[mt][2]), "=r"(afrag[mt][3])
                    : "r"(addr));
            }
            #pragma unroll
            for (int np = 0; np < 8; np++) {      // 8 groups of 2 n-tiles
                u32 addr = (u32)__cvta_generic_to_shared(
                    &bs[(b_row + np * 16) * LDSW + ks * 16 + b_col]);
                u32 bt0, bt1, bt2, bt3;
                asm volatile("ldmatrix.sync.aligned.m8n8.x4.shared.b16 {%0,%1,%2,%3}, [%4];\n"
                    : "=r"(bt0), "=r"(bt1), "=r"(bt2), "=r"(bt3) : "r"(addr));
                #pragma unroll
                for (int mt = 0; mt < 4; mt++) {
                    asm volatile(
                        "mma.sync.aligned.m16n8k16.row.col.f16.f16.f16.f16 "
                        "{%0,%1}, {%2,%3,%4,%5}, {%6,%7}, {%0,%1};\n"
                        : "+r"(acc[mt][np * 2][0]), "+r"(acc[mt][np * 2][1])
                        : "r"(afrag[mt][0]), "r"(afrag[mt][1]),
                          "r"(afrag[mt][2]), "r"(afrag[mt][3]),
                          "r"(bt0), "r"(bt1));
                    asm volatile(
                        "mma.sync.aligned.m16n8k16.row.col.f16.f16.f16.f16 "
                        "{%0,%1}, {%2,%3,%4,%5}, {%6,%7}, {%0,%1};\n"
                        : "+r"(acc[mt][np * 2 + 1][0]), "+r"(acc[mt][np * 2 + 1][1])
                        : "r"(afrag[mt][0]), "r"(afrag[mt][1]),
                          "r"(afrag[mt][2]), "r"(afrag[mt][3]),
                          "r"(bt2), "r"(bt3));
                }
            }
        }
        if (kt + 2 < KT) issue(kt + 2);
    }

    // --- epilogue ---
    const int m0 = blockIdx.y * BM + wm, n0 = blockIdx.x * BN + wn;
    OutT* Cb = C + (size_t)bz * sC;
    const float* Rb = resid ? resid + (size_t)bz * sR : nullptr;
    #pragma unroll
    for (int mt = 0; mt < 4; mt++) {
        #pragma unroll
        for (int hh = 0; hh < 2; hh++) {
            int m = m0 + mt * 16 + (lane >> 2) + hh * 8;
            float bm = bias_m ? bias_m[m] : 0.f;
            #pragma unroll
            for (int nt = 0; nt < 16; nt++) {
                int n = n0 + nt * 8 + (lane & 3) * 2;
                float2 f = __half22float2(*reinterpret_cast<__half2*>(&acc[mt][nt][hh]));
                float v0 = alpha * f.x + bm;
                float v1 = alpha * f.y + bm;
                if (bias_n) { v0 += bias_n[n]; v1 += bias_n[n + 1]; }
                size_t idx = (size_t)m * N + n;
                if (Rb) { v0 += Rb[idx]; v1 += Rb[idx + 1]; }
                store2(&Cb[idx], v0, v1);
            }
        }
    }
}

// ---------------- row softmax: one warp per row, fp16 in/out ----------------
__global__ void __launch_bounds__(256)
softmax_kernel(const __half* __restrict__ s, __half* __restrict__ p) {
    const int warp = threadIdx.x >> 5, lane = threadIdx.x & 31;
    const size_t row = (size_t)blockIdx.x * 8 + warp;
    const __half* sp = s + row * NTOK;
    __half* pp = p + row * NTOK;

    uint4 raw[4];
    #pragma unroll
    for (int i = 0; i < 4; i++)
        raw[i] = reinterpret_cast<const uint4*>(sp)[lane + 32 * i];

    float v[32];
    #pragma unroll
    for (int i = 0; i < 4; i++) {
        const __half* e = reinterpret_cast<const __half*>(&raw[i]);
        #pragma unroll
        for (int j = 0; j < 8; j++) v[i * 8 + j] = __half2float(e[j]);
    }

    float mx = -1e30f;
    #pragma unroll
    for (int i = 0; i < 32; i++) mx = fmaxf(mx, v[i]);
    #pragma unroll
    for (int o = 16; o > 0; o >>= 1)
        mx = fmaxf(mx, __shfl_xor_sync(0xffffffffu, mx, o));

    float sum = 0.f;
    #pragma unroll
    for (int i = 0; i < 32; i++) { v[i] = __expf(v[i] - mx); sum += v[i]; }
    #pragma unroll
    for (int o = 16; o > 0; o >>= 1)
        sum += __shfl_xor_sync(0xffffffffu, sum, o);

    const float inv = __frcp_rn(sum);
    uint4 outw[4];
    #pragma unroll
    for (int i = 0; i < 4; i++) {
        __half2* e = reinterpret_cast<__half2*>(&outw[i]);
        #pragma unroll
        for (int j = 0; j < 4; j++)
            e[j] = __floats2half2_rn(v[i * 8 + 2 * j] * inv, v[i * 8 + 2 * j + 1] * inv);
        reinterpret_cast<uint4*>(pp)[lane + 32 * i] = outw[i];
    }
}

extern "C" void kernel_launch(void* const* d_in, const int* in_sizes, int n_in,
                              void* d_out, int out_size) {
    (void)in_sizes; (void)n_in; (void)out_size;
    const float* x  = (const float*)d_in[0];
    const float* gw = (const float*)d_in[1];
    const float* gb = (const float*)d_in[2];
    const float* wq = (const float*)d_in[3];
    const float* bq = (const float*)d_in[4];
    const float* wk = (const float*)d_in[5];
    const float* bk = (const float*)d_in[6];
    const float* wv = (const float*)d_in[7];
    const float* bv = (const float*)d_in[8];
    const float* wp = (const float*)d_in[9];
    const float* bp = (const float*)d_in[10];
    float* out = (float*)d_out;

    __half *h, *q, *k, *vt, *s, *p, *o, *w;
    cudaGetSymbolAddress((void**)&h,  g_h);
    cudaGetSymbolAddress((void**)&q,  g_q);
    cudaGetSymbolAddress((void**)&k,  g_k);
    cudaGetSymbolAddress((void**)&vt, g_vt);
    cudaGetSymbolAddress((void**)&s,  g_s);
    cudaGetSymbolAddress((void**)&p,  g_p);
    cudaGetSymbolAddress((void**)&o,  g_o);
    cudaGetSymbolAddress((void**)&w,  g_w);

    cudaFuncSetAttribute(mma_gemm<__half>, cudaFuncAttributeMaxDynamicSharedMemorySize, GEMM_SMEM);
    cudaFuncSetAttribute(mma_gemm<float>,  cudaFuncAttributeMaxDynamicSharedMemorySize, GEMM_SMEM);

    const long NC = (long)NTOK * CH;
    const long SS = (long)NTOK * NTOK;

    convw_kernel<<<(CH * CH + 255) / 256, 256>>>(wq, wk, wv, wp, w);
    gn_kernel<<<BATCH * NGRP, 256>>>(x, gw, gb, h);

    // q[t][c]: M=NTOK, N=CH, K=CH (bias on n)
    dim3 gQ(CH / BN, NTOK / BM, BATCH);       // (2,8,32)
    mma_gemm<__half><<<gQ, NTHR, GEMM_SMEM>>>(h, w,           q, CH, CH, NC, 0, NC,
                                              1.f, nullptr, bq, nullptr, 0);
    mma_gemm<__half><<<gQ, NTHR, GEMM_SMEM>>>(h, w + CH * CH, k, CH, CH, NC, 0, NC,
                                              1.f, nullptr, bk, nullptr, 0);
    // vt[c][t]: M=CH, N=NTOK, K=CH (bias on m)
    dim3 gV(NTOK / BN, CH / BM, BATCH);       // (4,4,32)
    mma_gemm<__half><<<gV, NTHR, GEMM_SMEM>>>(w + 2 * CH * CH, h, vt, CH, NTOK, 0, NC, NC,
                                              1.f, bv, nullptr, nullptr, 0);

    // scores S[tq][tk] (fp16): M=N=NTOK, K=CH
    dim3 gS(NTOK / BN, NTOK / BM, BATCH);     // (4,8,32)
    const float scale = 1.0f / sqrtf((float)CH);
    mma_gemm<__half><<<gS, NTHR, GEMM_SMEM>>>(q, k, s, CH, NTOK, NC, NC, SS,
                                              scale, nullptr, nullptr, nullptr, 0);

    softmax_kernel<<<BATCH * NTOK / 8, 256>>>(s, p);

    // o[tq][c] = P . vt : M=NTOK, N=CH, K=NTOK
    dim3 gO(CH / BN, NTOK / BM, BATCH);       // (2,8,32)
    mma_gemm<__half><<<gO, NTHR, GEMM_SMEM>>>(p, vt, o, NTOK, CH, SS, NC, NC,
                                              1.f, nullptr, nullptr, nullptr, 0);

    // out[c][t] = x + (wp*1024 . o)/1024 + bp : M=CH, N=NTOK, K=CH
    dim3 gP(NTOK / BN, CH / BM, BATCH);       // (4,4,32)
    mma_gemm<float><<<gP, NTHR, GEMM_SMEM>>>(w + 3 * CH * CH, o, out, CH, NTOK, 0, NC, NC,
                                             1.f / 1024.f, bp, nullptr, x, NC);
}